// round 7
// baseline (speedup 1.0000x reference)
#include <cuda_runtime.h>
#include <cstdint>
#include <cstddef>

// Problem constants
#define NB 32
#define NT 512
#define NI 256
#define NH 512

// -------------------- device scratch (no allocations allowed) --------------------
// xp layout: [d][t][row(2048)][b(32)], row = unit*4 + gate  (gate: 0=i,1=f,2=g,3=o)
__device__ float    g_xp[2u * 512u * 2048u * 32u];   // 268 MB
// h double buffer per direction: [d][buf][k(512)][b(32)]
__device__ float    g_h[2 * 2 * 512 * 32];
// per-producer step flags: flag[d][p] at stride 32 u32 (128B apart). Producer p of
// direction d sets flag = s+1 after publishing its h slice for step s.
__device__ unsigned g_flags[2 * 64 * 32];

// -------------------- f32x2 helpers --------------------
__device__ __forceinline__ unsigned long long pk2(float a, float b) {
    unsigned long long r;
    asm("mov.b64 %0, {%1,%2};" : "=l"(r) : "f"(a), "f"(b));
    return r;
}
__device__ __forceinline__ void upk2(unsigned long long v, float& a, float& b) {
    asm("mov.b64 {%0,%1}, %2;" : "=f"(a), "=f"(b) : "l"(v));
}
__device__ __forceinline__ void fma2(unsigned long long& d, unsigned long long a, unsigned long long b) {
    asm("fma.rn.f32x2 %0, %1, %2, %0;" : "+l"(d) : "l"(a), "l"(b));
}
__device__ __forceinline__ void add2(unsigned long long& d, unsigned long long a) {
    asm("add.rn.f32x2 %0, %0, %1;" : "+l"(d) : "l"(a));
}

__device__ __forceinline__ float sigmoidf_(float x) {
    return 1.0f / (1.0f + __expf(-x));
}
__device__ __forceinline__ float tanh_fast(float x) {
    float r;
    asm("tanh.approx.f32 %0, %1;" : "=f"(r) : "f"(x));
    return r;
}

__device__ __forceinline__ unsigned ld_acquire_gpu(const unsigned* p) {
    unsigned v;
    asm volatile("ld.acquire.gpu.u32 %0, [%1];" : "=r"(v) : "l"(p) : "memory");
    return v;
}
__device__ __forceinline__ void st_release_gpu(unsigned* p, unsigned v) {
    asm volatile("st.release.gpu.u32 [%0], %1;" :: "l"(p), "r"(v) : "memory");
}

// ==================================================================================
// Phase A: input projections (init fused into first 8 blocks).
// xp[d][t][row][b] = sum_i x[b][t][i]*W_ih[d][wrow][i] + bias
// where row = unit*4+gate and wrow = gate*512 + unit.
// Block: (t-chunk of 32) x (64 rows) x (direction).  256 threads, 8 warps.
// ==================================================================================
#define XPROJ_SMEM (65536 + 64 * 33 * 16)  // 64KB packed weights + padded x tile

__global__ __launch_bounds__(256, 2) void k_xproj(
    const float* __restrict__ x,
    const float* __restrict__ Wf, const float* __restrict__ bf,
    const float* __restrict__ Wb, const float* __restrict__ bb)
{
    extern __shared__ char smem[];
    unsigned long long* sW = (unsigned long long*)smem;        // [256][32] u64 pairs (64KB)
    float*              fW = (float*)smem;                     // alias: fW[k*64 + lr]
    float4*             sX = (float4*)(smem + 65536);          // [k4(64)*33 + b] padded

    const int d    = blockIdx.z;
    const float* W    = d ? Wb : Wf;
    const float* bias = d ? bb : bf;
    const int R0   = blockIdx.y * 64;
    const int t0   = blockIdx.x * 32;
    const int tid  = threadIdx.x;
    const int lane = tid & 31;
    const int w    = tid >> 5;

    // ---- fused init: zero h buffer 0 of both directions + reset flags
    if (blockIdx.z == 0 && blockIdx.y == 0 && blockIdx.x < 8) {
        int t = blockIdx.x * 256 + tid;   // 2048 threads
        #pragma unroll
        for (int i = 0; i < 8; i++) {
            g_h[t + i * 2048]         = 0.0f;   // dir 0, buf 0 (16384 floats)
            g_h[32768 + t + i * 2048] = 0.0f;   // dir 1, buf 0
        }
        #pragma unroll
        for (int i = 0; i < 2; i++)
            g_flags[t + i * 2048] = 0u;         // 4096 flag words
    }

    // ---- load + pack weight slice: fW[k*64 + lr] = W[wrow(R0+lr)][k]
    {
        int lr   = tid & 63;
        int kb   = (tid >> 6) * 64;
        int grow = R0 + lr;
        int wrow = ((grow & 3) << 9) + (grow >> 2);
        const float* src = W + wrow * 256 + kb;
        #pragma unroll 8
        for (int k = 0; k < 64; k++)
            fW[(kb + k) * 64 + lr] = src[k];
    }

    // ---- per-thread bias values for its 8 rows
    float bv[8];
    #pragma unroll
    for (int r = 0; r < 8; r++) {
        int grow = R0 + w * 8 + r;
        bv[r] = bias[((grow & 3) << 9) + (grow >> 2)];
    }
    __syncthreads();

    for (int tl = 0; tl < 32; tl++) {
        int t = t0 + tl;
        __syncthreads();  // previous tile fully consumed
        // ---- load x tile: sX[k4*33 + b] = x[b][t][k4*4 .. +3]
        #pragma unroll
        for (int bi = 0; bi < 4; bi++) {
            int b = w + bi * 8;
            #pragma unroll
            for (int kh = 0; kh < 2; kh++) {
                int k4 = kh * 32 + lane;
                float4 v = *(const float4*)(x + ((size_t)(b * 512 + t)) * 256 + k4 * 4);
                sX[k4 * 33 + b] = v;
            }
        }
        __syncthreads();

        unsigned long long acc0 = 0, acc1 = 0, acc2 = 0, acc3 = 0;
        const unsigned long long* wbase = sW + w * 4;
        #pragma unroll 4
        for (int k4 = 0; k4 < 64; k4++) {
            float4 xv = sX[k4 * 33 + lane];
            #pragma unroll
            for (int kk = 0; kk < 4; kk++) {
                float xs = (&xv.x)[kk];
                unsigned long long hh = pk2(xs, xs);
                const unsigned long long* wp = wbase + (k4 * 4 + kk) * 32;
                ulonglong2 wa = *(const ulonglong2*)(wp);
                ulonglong2 wc = *(const ulonglong2*)(wp + 2);
                fma2(acc0, hh, wa.x);
                fma2(acc1, hh, wa.y);
                fma2(acc2, hh, wc.x);
                fma2(acc3, hh, wc.y);
            }
        }

        // ---- store 8 rows (coalesced over lanes = batch)
        float* outp = g_xp + ((((size_t)d * 512 + t) * 2048) + R0) * 32 + lane;
        float f0, f1;
        upk2(acc0, f0, f1);
        outp[(w * 8 + 0) * 32] = f0 + bv[0];
        outp[(w * 8 + 1) * 32] = f1 + bv[1];
        upk2(acc1, f0, f1);
        outp[(w * 8 + 2) * 32] = f0 + bv[2];
        outp[(w * 8 + 3) * 32] = f1 + bv[3];
        upk2(acc2, f0, f1);
        outp[(w * 8 + 4) * 32] = f0 + bv[4];
        outp[(w * 8 + 5) * 32] = f1 + bv[5];
        upk2(acc3, f0, f1);
        outp[(w * 8 + 6) * 32] = f0 + bv[6];
        outp[(w * 8 + 7) * 32] = f1 + bv[7];
    }
}

// ==================================================================================
// Phase B: persistent recurrent kernel (v5: barrier-free flag dataflow).
// 128 blocks, 96KB smem, 1 block/SM, all co-resident => spin-safe.
// Block bid: d = bid>>6, p = bid&63 owns hidden units j0 = p*8 .. +8 of direction d.
// NO grid barrier. Producer p publishes its 8 h values for step s, then
// release-stores flag[d][p] = s+1. Consumers: warp w needs k in [64w,64w+64) =
// producer chunks 8w..8w+8 only; it acquire-polls each chunk's flag (>= s) and
// streams that chunk's 8 k-columns through the FMA pipe as it arrives.
// Safety: a producer's write of buffer parity P for step s happens only after it
// read ALL chunks of step s-1 (data dependence through the gate sums), so
// flag[q] >= s implies q is done reading the buffer being overwritten.
// Compute core = v3 pattern: weights broadcast LDS.128 (conflict-free), h loads
// coalesced 128B lines, 16 fma2 per k per lane. 8-way cross-warp reduce in smem.
// ==================================================================================
#define RECUR_SMEM (65536 + 32768)  // W_hh pairs (64KB) + reduce staging (32KB)

__global__ __launch_bounds__(256, 1) void k_recur(
    const float* __restrict__ Whf,
    const float* __restrict__ Whb,
    float* __restrict__ out)
{
    extern __shared__ char smem[];
    ulonglong2*         wS  = (ulonglong2*)smem;                      // [512*8]  64KB
    unsigned long long* red = (unsigned long long*)(smem + 65536);    // [8][8][2][32] 32KB

    const int bid  = blockIdx.x;
    const int d    = bid >> 6;
    const int j0   = (bid & 63) * 8;
    const int tid  = threadIdx.x;
    const int lane = tid & 31;
    const int w    = tid >> 5;
    const float* Wh = d ? Whb : Whf;

    // ---- load + pack W_hh slice: wS[k*8+j] = { (wi,wf), (wg,wo) } for unit j0+j
    for (int idx = tid; idx < 512 * 8; idx += 256) {
        int k  = idx >> 3;
        int j  = idx & 7;
        int jg = j0 + j;
        float wi = Wh[((0 * 512) + jg) * 512 + k];
        float wf = Wh[((1 * 512) + jg) * 512 + k];
        float wg = Wh[((2 * 512) + jg) * 512 + k];
        float wo = Wh[((3 * 512) + jg) * 512 + k];
        ulonglong2 v;
        v.x = pk2(wi, wf);
        v.y = pk2(wg, wo);
        wS[idx] = v;
    }
    __syncthreads();

    const int jg_fin = j0 + w;                  // finalize role: unit = warp id, batch = lane
    float*    hbufs  = g_h + d * 2 * 512 * 32;
    unsigned* flags  = g_flags + d * 64 * 32;   // flag[q] at flags[q*32]
    unsigned* myflag = g_flags + (size_t)bid * 32;
    float     cst = 0.0f;

    // prefetch xp for step 0
    float xp_i, xp_f, xp_g, xp_o;
    {
        const int tt0 = d ? 511 : 0;
        const float* xpp = g_xp + (((size_t)d * 512 + tt0) * 2048 + (size_t)jg_fin * 4) * 32 + lane;
        xp_i = xpp[0]; xp_f = xpp[32]; xp_g = xpp[64]; xp_o = xpp[96];
    }

    for (int s = 0; s < 512; s++) {
        const int tt = d ? (511 - s) : s;
        const float* hsrc = hbufs + (s & 1) * 16384;

        ulonglong2 acc[8];
        #pragma unroll
        for (int j = 0; j < 8; j++) { acc[j].x = 0ull; acc[j].y = 0ull; }

        // ---- stream this warp's 8 producer chunks (8 k each), flag-gated
        #pragma unroll 2
        for (int p = 0; p < 8; p++) {
            const int cp = 8 * w + p;           // producer / chunk index
            // acquire-poll: chunk cp's h for step s is ready when flag >= s
            while (ld_acquire_gpu(flags + cp * 32) < (unsigned)s) { }

            const float* hp = hsrc + cp * 8 * 32 + lane;
            float hk[8];
            #pragma unroll
            for (int i = 0; i < 8; i++) hk[i] = hp[i * 32];

            const ulonglong2* wp = wS + cp * 8 * 8;
            #pragma unroll
            for (int i = 0; i < 8; i++) {
                unsigned long long hh = pk2(hk[i], hk[i]);
                const ulonglong2* wk = wp + i * 8;
                #pragma unroll
                for (int j = 0; j < 8; j++) {
                    ulonglong2 wv = wk[j];
                    fma2(acc[j].x, hh, wv.x);
                    fma2(acc[j].y, hh, wv.y);
                }
            }
        }

        // ---- stage partials: red[w][j][0/1][lane]
        #pragma unroll
        for (int j = 0; j < 8; j++) {
            red[(((w * 8 + j) * 2) + 0) * 32 + lane] = acc[j].x;
            red[(((w * 8 + j) * 2) + 1) * 32 + lane] = acc[j].y;
        }
        __syncthreads();

        // ---- finalize: warp w = unit j0+w, lane = batch
        unsigned long long s0 = 0ull, s1 = 0ull;
        #pragma unroll
        for (int ww = 0; ww < 8; ww++) {
            add2(s0, red[(((ww * 8 + w) * 2) + 0) * 32 + lane]);
            add2(s1, red[(((ww * 8 + w) * 2) + 1) * 32 + lane]);
        }
        float gi, gf, gg, go;
        upk2(s0, gi, gf);
        upk2(s1, gg, go);

        gi += xp_i; gf += xp_f; gg += xp_g; go += xp_o;
        gi = sigmoidf_(gi);
        gf = sigmoidf_(gf);
        go = sigmoidf_(go);
        gg = tanh_fast(gg);
        cst = gf * cst + gi * gg;
        float h = go * tanh_fast(cst);

        // publish h for next step (coalesced: [k][b]); output (write-through)
        hbufs[((s + 1) & 1) * 16384 + jg_fin * 32 + lane] = h;
        out[((size_t)lane * 512 + tt) * 1024 + d * 512 + jg_fin] = h;

        // ---- prefetch xp for step s+1 (latency overlaps flag publish/poll)
        if (s + 1 < 512) {
            const int ttn = d ? (510 - s) : (s + 1);
            const float* xpp = g_xp + (((size_t)d * 512 + ttn) * 2048 + (size_t)jg_fin * 4) * 32 + lane;
            xp_i = xpp[0]; xp_f = xpp[32]; xp_g = xpp[64]; xp_o = xpp[96];
        }

        // ---- all h writes of this block done -> release flag = s+1
        __syncthreads();
        if (tid == 0) st_release_gpu(myflag, (unsigned)(s + 1));
    }
}

// ==================================================================================
extern "C" void kernel_launch(void* const* d_in, const int* in_sizes, int n_in,
                              void* d_out, int out_size)
{
    const float* x    = (const float*)d_in[0];
    const float* Wihf = (const float*)d_in[1];
    const float* Whhf = (const float*)d_in[2];
    const float* bf   = (const float*)d_in[3];
    const float* Wihb = (const float*)d_in[4];
    const float* Whhb = (const float*)d_in[5];
    const float* bb   = (const float*)d_in[6];
    float* out = (float*)d_out;

    cudaFuncSetAttribute(k_xproj, cudaFuncAttributeMaxDynamicSharedMemorySize, XPROJ_SMEM);
    cudaFuncSetAttribute(k_recur, cudaFuncAttributeMaxDynamicSharedMemorySize, RECUR_SMEM);

    k_xproj<<<dim3(16, 32, 2), 256, XPROJ_SMEM>>>(x, Wihf, bf, Wihb, bb);
    k_recur<<<128, 256, RECUR_SMEM>>>(Whhf, Whhb, out);
}

// round 8
// speedup vs baseline: 1.0956x; 1.0956x over previous
#include <cuda_runtime.h>
#include <cstdint>
#include <cstddef>

// Problem constants
#define NB 32
#define NT 512
#define NI 256
#define NH 512

// -------------------- device scratch (no allocations allowed) --------------------
// xp layout: [d][t][row(2048)][b(32)], row = unit*4 + gate  (gate: 0=i,1=f,2=g,3=o)
__device__ float    g_xp[2u * 512u * 2048u * 32u];   // 268 MB
// h double buffer per direction: [d][buf][k(512)][b(32)]
__device__ float    g_h[2 * 2 * 512 * 32];
// per-producer step flags: flag[d][p] at stride 32 u32 (128B apart). Producer p of
// direction d sets flag = s+1 after publishing its h slice for step s.
__device__ unsigned g_flags[2 * 64 * 32];

// -------------------- f32x2 helpers --------------------
__device__ __forceinline__ unsigned long long pk2(float a, float b) {
    unsigned long long r;
    asm("mov.b64 %0, {%1,%2};" : "=l"(r) : "f"(a), "f"(b));
    return r;
}
__device__ __forceinline__ void upk2(unsigned long long v, float& a, float& b) {
    asm("mov.b64 {%0,%1}, %2;" : "=f"(a), "=f"(b) : "l"(v));
}
__device__ __forceinline__ void fma2(unsigned long long& d, unsigned long long a, unsigned long long b) {
    asm("fma.rn.f32x2 %0, %1, %2, %0;" : "+l"(d) : "l"(a), "l"(b));
}
__device__ __forceinline__ void add2(unsigned long long& d, unsigned long long a) {
    asm("add.rn.f32x2 %0, %0, %1;" : "+l"(d) : "l"(a));
}

__device__ __forceinline__ float sigmoidf_(float x) {
    return 1.0f / (1.0f + __expf(-x));
}
__device__ __forceinline__ float tanh_fast(float x) {
    float r;
    asm("tanh.approx.f32 %0, %1;" : "=f"(r) : "f"(x));
    return r;
}

__device__ __forceinline__ unsigned ld_acquire_gpu(const unsigned* p) {
    unsigned v;
    asm volatile("ld.acquire.gpu.u32 %0, [%1];" : "=r"(v) : "l"(p) : "memory");
    return v;
}
__device__ __forceinline__ void st_release_gpu(unsigned* p, unsigned v) {
    asm volatile("st.release.gpu.u32 [%0], %1;" :: "l"(p), "r"(v) : "memory");
}

// ==================================================================================
// Phase A: input projections (init fused into first 8 blocks).  (unchanged, proven)
// ==================================================================================
#define XPROJ_SMEM (65536 + 64 * 33 * 16)  // 64KB packed weights + padded x tile

__global__ __launch_bounds__(256, 2) void k_xproj(
    const float* __restrict__ x,
    const float* __restrict__ Wf, const float* __restrict__ bf,
    const float* __restrict__ Wb, const float* __restrict__ bb)
{
    extern __shared__ char smem[];
    unsigned long long* sW = (unsigned long long*)smem;        // [256][32] u64 pairs (64KB)
    float*              fW = (float*)smem;                     // alias: fW[k*64 + lr]
    float4*             sX = (float4*)(smem + 65536);          // [k4(64)*33 + b] padded

    const int d    = blockIdx.z;
    const float* W    = d ? Wb : Wf;
    const float* bias = d ? bb : bf;
    const int R0   = blockIdx.y * 64;
    const int t0   = blockIdx.x * 32;
    const int tid  = threadIdx.x;
    const int lane = tid & 31;
    const int w    = tid >> 5;

    // ---- fused init: zero h buffer 0 of both directions + reset flags
    if (blockIdx.z == 0 && blockIdx.y == 0 && blockIdx.x < 8) {
        int t = blockIdx.x * 256 + tid;   // 2048 threads
        #pragma unroll
        for (int i = 0; i < 8; i++) {
            g_h[t + i * 2048]         = 0.0f;   // dir 0, buf 0 (16384 floats)
            g_h[32768 + t + i * 2048] = 0.0f;   // dir 1, buf 0
        }
        #pragma unroll
        for (int i = 0; i < 2; i++)
            g_flags[t + i * 2048] = 0u;         // 4096 flag words
    }

    // ---- load + pack weight slice: fW[k*64 + lr] = W[wrow(R0+lr)][k]
    {
        int lr   = tid & 63;
        int kb   = (tid >> 6) * 64;
        int grow = R0 + lr;
        int wrow = ((grow & 3) << 9) + (grow >> 2);
        const float* src = W + wrow * 256 + kb;
        #pragma unroll 8
        for (int k = 0; k < 64; k++)
            fW[(kb + k) * 64 + lr] = src[k];
    }

    // ---- per-thread bias values for its 8 rows
    float bv[8];
    #pragma unroll
    for (int r = 0; r < 8; r++) {
        int grow = R0 + w * 8 + r;
        bv[r] = bias[((grow & 3) << 9) + (grow >> 2)];
    }
    __syncthreads();

    for (int tl = 0; tl < 32; tl++) {
        int t = t0 + tl;
        __syncthreads();  // previous tile fully consumed
        // ---- load x tile: sX[k4*33 + b] = x[b][t][k4*4 .. +3]
        #pragma unroll
        for (int bi = 0; bi < 4; bi++) {
            int b = w + bi * 8;
            #pragma unroll
            for (int kh = 0; kh < 2; kh++) {
                int k4 = kh * 32 + lane;
                float4 v = *(const float4*)(x + ((size_t)(b * 512 + t)) * 256 + k4 * 4);
                sX[k4 * 33 + b] = v;
            }
        }
        __syncthreads();

        unsigned long long acc0 = 0, acc1 = 0, acc2 = 0, acc3 = 0;
        const unsigned long long* wbase = sW + w * 4;
        #pragma unroll 4
        for (int k4 = 0; k4 < 64; k4++) {
            float4 xv = sX[k4 * 33 + lane];
            #pragma unroll
            for (int kk = 0; kk < 4; kk++) {
                float xs = (&xv.x)[kk];
                unsigned long long hh = pk2(xs, xs);
                const unsigned long long* wp = wbase + (k4 * 4 + kk) * 32;
                ulonglong2 wa = *(const ulonglong2*)(wp);
                ulonglong2 wc = *(const ulonglong2*)(wp + 2);
                fma2(acc0, hh, wa.x);
                fma2(acc1, hh, wa.y);
                fma2(acc2, hh, wc.x);
                fma2(acc3, hh, wc.y);
            }
        }

        // ---- store 8 rows (coalesced over lanes = batch)
        float* outp = g_xp + ((((size_t)d * 512 + t) * 2048) + R0) * 32 + lane;
        float f0, f1;
        upk2(acc0, f0, f1);
        outp[(w * 8 + 0) * 32] = f0 + bv[0];
        outp[(w * 8 + 1) * 32] = f1 + bv[1];
        upk2(acc1, f0, f1);
        outp[(w * 8 + 2) * 32] = f0 + bv[2];
        outp[(w * 8 + 3) * 32] = f1 + bv[3];
        upk2(acc2, f0, f1);
        outp[(w * 8 + 4) * 32] = f0 + bv[4];
        outp[(w * 8 + 5) * 32] = f1 + bv[5];
        upk2(acc3, f0, f1);
        outp[(w * 8 + 6) * 32] = f0 + bv[6];
        outp[(w * 8 + 7) * 32] = f1 + bv[7];
    }
}

// ==================================================================================
// Phase B: persistent recurrent kernel (v6: register-tiled GEMM core).
// 128 CTAs x 256 thr, 1 CTA/SM (140KB smem), all co-resident => spin-safe.
// CTA bid: d = bid>>6, owns 8 units j0 = (bid&63)*8 of direction d.
// Thread map: kg = tid>>6 (4 k-groups of 128), pos = tid&63 = (u = pos>>3, b4 = pos&7).
// Each thread owns the full 4-gate x 4-batch tile of unit j0+u, batches 4*b4..+4,
// accumulated over its 128-k slice:
//   per k: 1 LDS.128 (all 4 gate weights of u, pre-paired (i,f),(g,o))
//        + 1 LDS.128 (4 h values) + 4 pk2 + 8 fma2   => 14 instrs / 16 fma-cycles.
// 4-way kg reduce via smem (12KB), finalize fully thread-local (kg==0 threads own
// all gates of (u, 4 batches); c[4] in registers; STG.128 h publish).
// Flag dataflow: poll all 64 producer flags >= s, stage h 64KB into smem, compute.
// ==================================================================================
#define RECUR_W_BYTES  65536              // wS: [512][16] u64
#define RECUR_H_BYTES  65536              // hS: [512][32] f32
#define RECUR_RED_U64  (8 * 3 * 64)       // red: [j(8)][kg-1(3)][pos(64)] u64
#define RECUR_SMEM     (RECUR_W_BYTES + RECUR_H_BYTES + RECUR_RED_U64 * 8)

__global__ __launch_bounds__(256, 1) void k_recur(
    const float* __restrict__ Whf,
    const float* __restrict__ Whb,
    float* __restrict__ out)
{
    extern __shared__ char smem[];
    unsigned long long* wS  = (unsigned long long*)smem;                 // [512][16]
    float*              hS  = (float*)(smem + RECUR_W_BYTES);            // [512][32]
    unsigned long long* red = (unsigned long long*)(smem + RECUR_W_BYTES + RECUR_H_BYTES);

    const int bid  = blockIdx.x;
    const int d    = bid >> 6;
    const int j0   = (bid & 63) * 8;
    const int tid  = threadIdx.x;
    const int kg   = tid >> 6;         // 0..3
    const int pos  = tid & 63;
    const int u    = pos >> 3;         // 0..7  unit within CTA
    const int b4   = pos & 7;          // 0..7  batch quad
    const float* Wh = d ? Whb : Whf;

    // ---- load + pack W_hh slice: wS[k*16 + u*2 + gp] = (w_i,w_f) / (w_g,w_o)
    for (int idx = tid; idx < 512 * 8; idx += 256) {
        int k  = idx >> 3;
        int j  = idx & 7;
        int jg = j0 + j;
        float wi = Wh[((0 * 512) + jg) * 512 + k];
        float wf = Wh[((1 * 512) + jg) * 512 + k];
        float wg = Wh[((2 * 512) + jg) * 512 + k];
        float wo = Wh[((3 * 512) + jg) * 512 + k];
        wS[k * 16 + j * 2 + 0] = pk2(wi, wf);
        wS[k * 16 + j * 2 + 1] = pk2(wg, wo);
    }
    __syncthreads();

    float*    hbufs  = g_h + d * 2 * 512 * 32;
    unsigned* flags  = g_flags + d * 64 * 32;    // flag[q] at flags[q*32]
    unsigned* myflag = g_flags + (size_t)bid * 32;

    const int jg_fin = j0 + u;                   // finalize unit (kg==0 threads)
    float c0 = 0.f, c1 = 0.f, c2 = 0.f, c3 = 0.f;

    // xp prefetch for step 0 (kg==0 threads: 4 gates x 4 batches)
    float4 xpi, xpf, xpg, xpo;
    {
        const int tt0 = d ? 511 : 0;
        const float* xpp = g_xp + (((size_t)d * 512 + tt0) * 2048 + (size_t)jg_fin * 4) * 32 + 4 * b4;
        xpi = *(const float4*)(xpp);
        xpf = *(const float4*)(xpp + 32);
        xpg = *(const float4*)(xpp + 64);
        xpo = *(const float4*)(xpp + 96);
    }

    const int kbase = kg * 128;

    for (int s = 0; s < 512; s++) {
        const int tt = d ? (511 - s) : s;

        // ---- wait for all producers of this direction to publish step-s h
        if (tid < 64) {
            while (ld_acquire_gpu(flags + tid * 32) < (unsigned)s) { }
        }
        __syncthreads();

        // ---- stage h (64KB) global -> smem, coalesced float4
        {
            const float4* src = (const float4*)(hbufs + (s & 1) * 16384);
            float4* dst = (float4*)hS;
            #pragma unroll
            for (int i = 0; i < 16; i++)
                dst[tid + i * 256] = src[tid + i * 256];
        }
        __syncthreads();

        // ---- register-tiled accumulation over this thread's 128-k slice
        ulonglong2 acc[4];   // acc[e].x = (i,f), acc[e].y = (g,o) for batch 4*b4+e
        #pragma unroll
        for (int e = 0; e < 4; e++) { acc[e].x = 0ull; acc[e].y = 0ull; }

        {
            const ulonglong2* wp = (const ulonglong2*)(wS + u * 2) + kbase * 8; // stride 8 ull2/k
            const float4*     hp = (const float4*)(hS + 4 * b4) + kbase * 8;    // stride 8 f4/k
            #pragma unroll 8
            for (int kl = 0; kl < 128; kl++) {
                ulonglong2 wv = wp[kl * 8];
                float4     hv = hp[kl * 8];
                #pragma unroll
                for (int e = 0; e < 4; e++) {
                    unsigned long long hh = pk2((&hv.x)[e], (&hv.x)[e]);
                    fma2(acc[e].x, hh, wv.x);
                    fma2(acc[e].y, hh, wv.y);
                }
            }
        }

        // ---- 4-way kg reduce: kg>0 stage, kg==0 sums
        if (kg > 0) {
            #pragma unroll
            for (int e = 0; e < 4; e++) {
                red[((e * 2 + 0) * 3 + (kg - 1)) * 64 + pos] = acc[e].x;
                red[((e * 2 + 1) * 3 + (kg - 1)) * 64 + pos] = acc[e].y;
            }
        }
        __syncthreads();

        if (kg == 0) {
            #pragma unroll
            for (int e = 0; e < 4; e++) {
                #pragma unroll
                for (int q = 0; q < 3; q++) {
                    add2(acc[e].x, red[((e * 2 + 0) * 3 + q) * 64 + pos]);
                    add2(acc[e].y, red[((e * 2 + 1) * 3 + q) * 64 + pos]);
                }
            }

            // ---- finalize 4 batches of unit jg_fin
            float4 hv4;
            {
                float gi, gf, gg, go;
                upk2(acc[0].x, gi, gf); upk2(acc[0].y, gg, go);
                gi = sigmoidf_(gi + xpi.x); gf = sigmoidf_(gf + xpf.x);
                gg = tanh_fast(gg + xpg.x); go = sigmoidf_(go + xpo.x);
                c0 = gf * c0 + gi * gg;  hv4.x = go * tanh_fast(c0);

                upk2(acc[1].x, gi, gf); upk2(acc[1].y, gg, go);
                gi = sigmoidf_(gi + xpi.y); gf = sigmoidf_(gf + xpf.y);
                gg = tanh_fast(gg + xpg.y); go = sigmoidf_(go + xpo.y);
                c1 = gf * c1 + gi * gg;  hv4.y = go * tanh_fast(c1);

                upk2(acc[2].x, gi, gf); upk2(acc[2].y, gg, go);
                gi = sigmoidf_(gi + xpi.z); gf = sigmoidf_(gf + xpf.z);
                gg = tanh_fast(gg + xpg.z); go = sigmoidf_(go + xpo.z);
                c2 = gf * c2 + gi * gg;  hv4.z = go * tanh_fast(c2);

                upk2(acc[3].x, gi, gf); upk2(acc[3].y, gg, go);
                gi = sigmoidf_(gi + xpi.w); gf = sigmoidf_(gf + xpf.w);
                gg = tanh_fast(gg + xpg.w); go = sigmoidf_(go + xpo.w);
                c3 = gf * c3 + gi * gg;  hv4.w = go * tanh_fast(c3);
            }

            // publish h (one STG.128) + write output (4 scattered STG.32)
            *(float4*)(hbufs + ((s + 1) & 1) * 16384 + jg_fin * 32 + 4 * b4) = hv4;
            const size_t ob = (size_t)(4 * b4) * 512 * 1024 + (size_t)tt * 1024 + d * 512 + jg_fin;
            out[ob]                   = hv4.x;
            out[ob + 1 * 512 * 1024]  = hv4.y;
            out[ob + 2 * 512 * 1024]  = hv4.z;
            out[ob + 3 * 512 * 1024]  = hv4.w;

            // ---- prefetch xp for step s+1
            if (s + 1 < 512) {
                const int ttn = d ? (510 - s) : (s + 1);
                const float* xpp = g_xp + (((size_t)d * 512 + ttn) * 2048 + (size_t)jg_fin * 4) * 32 + 4 * b4;
                xpi = *(const float4*)(xpp);
                xpf = *(const float4*)(xpp + 32);
                xpg = *(const float4*)(xpp + 64);
                xpo = *(const float4*)(xpp + 96);
            }
        }

        // ---- all h writes of this CTA done -> release flag = s+1
        __syncthreads();
        if (tid == 0) st_release_gpu(myflag, (unsigned)(s + 1));
    }
}

// ==================================================================================
extern "C" void kernel_launch(void* const* d_in, const int* in_sizes, int n_in,
                              void* d_out, int out_size)
{
    const float* x    = (const float*)d_in[0];
    const float* Wihf = (const float*)d_in[1];
    const float* Whhf = (const float*)d_in[2];
    const float* bf   = (const float*)d_in[3];
    const float* Wihb = (const float*)d_in[4];
    const float* Whhb = (const float*)d_in[5];
    const float* bb   = (const float*)d_in[6];
    float* out = (float*)d_out;

    cudaFuncSetAttribute(k_xproj, cudaFuncAttributeMaxDynamicSharedMemorySize, XPROJ_SMEM);
    cudaFuncSetAttribute(k_recur, cudaFuncAttributeMaxDynamicSharedMemorySize, RECUR_SMEM);

    k_xproj<<<dim3(16, 32, 2), 256, XPROJ_SMEM>>>(x, Wihf, bf, Wihb, bb);
    k_recur<<<128, 256, RECUR_SMEM>>>(Whhf, Whhb, out);
}

// round 10
// speedup vs baseline: 1.4331x; 1.3081x over previous
#include <cuda_runtime.h>
#include <cuda_fp16.h>
#include <cstdint>
#include <cstddef>

// Problem constants
#define NB 32
#define NT 512
#define NI 256
#define NH 512

// -------------------- device scratch (no allocations allowed) --------------------
// xp layout: [d][t][b(32)][row(2048)], row = unit*4 + gate  (gate: 0=i,1=f,2=g,3=o)
__device__ float    g_xp[2u * 512u * 32u * 2048u];   // 268 MB
// h split-fp16 double buffer: [d][parity][op(hi/lo)][b(32)][k(512)] __half
__device__ __half   g_hs[2 * 2 * 2 * 32 * 512];
// per-producer step flags: flag[d][p] at stride 32 u32. 64 producers per dir.
__device__ unsigned g_flags[2 * 64 * 32];

// -------------------- helpers --------------------
__device__ __forceinline__ unsigned long long pk2(float a, float b) {
    unsigned long long r;
    asm("mov.b64 %0, {%1,%2};" : "=l"(r) : "f"(a), "f"(b));
    return r;
}
__device__ __forceinline__ void upk2(unsigned long long v, float& a, float& b) {
    asm("mov.b64 {%0,%1}, %2;" : "=f"(a), "=f"(b) : "l"(v));
}
__device__ __forceinline__ void fma2(unsigned long long& d, unsigned long long a, unsigned long long b) {
    asm("fma.rn.f32x2 %0, %1, %2, %0;" : "+l"(d) : "l"(a), "l"(b));
}
__device__ __forceinline__ float tanh_fast(float x) {
    float r;
    asm("tanh.approx.f32 %0, %1;" : "=f"(r) : "f"(x));
    return r;
}
__device__ __forceinline__ float sigmoid_t(float x) {   // 0.5 + 0.5*tanh(x/2)
    return 0.5f + 0.5f * tanh_fast(0.5f * x);
}
__device__ __forceinline__ unsigned ld_acquire_gpu(const unsigned* p) {
    unsigned v;
    asm volatile("ld.acquire.gpu.u32 %0, [%1];" : "=r"(v) : "l"(p) : "memory");
    return v;
}
__device__ __forceinline__ void st_release_gpu(unsigned* p, unsigned v) {
    asm volatile("st.release.gpu.u32 [%0], %1;" :: "l"(p), "r"(v) : "memory");
}
__device__ __forceinline__ uint32_t smem_to_u32(const void* smem_ptr) {
    uint32_t addr;
    asm("{ .reg .u64 tmp; cvta.to.shared.u64 tmp, %1; cvt.u32.u64 %0, tmp; }"
        : "=r"(addr) : "l"(smem_ptr));
    return addr;
}

// ldmatrix (sm_75+) and mma.sync m16n8k16 f16->f32 (sm_80+): valid on compute_103
__device__ __forceinline__ void ldm_x4(uint32_t& r0, uint32_t& r1, uint32_t& r2, uint32_t& r3,
                                       uint32_t addr) {
    asm volatile("ldmatrix.sync.aligned.m8n8.x4.shared.b16 {%0,%1,%2,%3}, [%4];"
        : "=r"(r0), "=r"(r1), "=r"(r2), "=r"(r3) : "r"(addr));
}
__device__ __forceinline__ void ldm_x2(uint32_t& r0, uint32_t& r1, uint32_t addr) {
    asm volatile("ldmatrix.sync.aligned.m8n8.x2.shared.b16 {%0,%1}, [%2];"
        : "=r"(r0), "=r"(r1) : "r"(addr));
}
__device__ __forceinline__ void mma16816(float* d, const uint32_t* a, const uint32_t* b) {
    asm volatile(
        "mma.sync.aligned.m16n8k16.row.col.f32.f16.f16.f32 "
        "{%0,%1,%2,%3}, {%4,%5,%6,%7}, {%8,%9}, {%0,%1,%2,%3};"
        : "+f"(d[0]), "+f"(d[1]), "+f"(d[2]), "+f"(d[3])
        : "r"(a[0]), "r"(a[1]), "r"(a[2]), "r"(a[3]), "r"(b[0]), "r"(b[1]));
}

// ==================================================================================
// Phase A: input projections (f32x2 core, proven). Init of g_hs/g_flags fused in.
// New xp output layout: [d][t][b][row] so recur finalize reads gates as one float4.
// ==================================================================================
#define XPROJ_SMEM (65536 + 64 * 33 * 16)

__global__ __launch_bounds__(256, 2) void k_xproj(
    const float* __restrict__ x,
    const float* __restrict__ Wf, const float* __restrict__ bf,
    const float* __restrict__ Wb, const float* __restrict__ bb)
{
    extern __shared__ char smem[];
    unsigned long long* sW = (unsigned long long*)smem;        // [256][32] u64 pairs (64KB)
    float*              fW = (float*)smem;
    float4*             sX = (float4*)(smem + 65536);

    const int d    = blockIdx.z;
    const float* W    = d ? Wb : Wf;
    const float* bias = d ? bb : bf;
    const int R0   = blockIdx.y * 64;
    const int t0   = blockIdx.x * 32;
    const int tid  = threadIdx.x;
    const int lane = tid & 31;
    const int w    = tid >> 5;

    // ---- fused init: zero g_hs parity 0 (both dirs, hi+lo) + flags
    if (blockIdx.z == 0 && blockIdx.y == 0 && blockIdx.x < 8) {
        int t = blockIdx.x * 256 + tid;   // 0..2047
        #pragma unroll
        for (int r = 0; r < 4; r++) {     // regions: (d,op) of parity 0
            int dd = r >> 1, op = r & 1;
            uint4* z = (uint4*)&g_hs[(((size_t)dd * 2 + 0) * 2 + op) * 32 * 512];
            z[t] = make_uint4(0, 0, 0, 0);
        }
        #pragma unroll
        for (int i = 0; i < 2; i++)
            g_flags[t + i * 2048] = 0u;   // 4096 flag words
    }

    // ---- load + pack weight slice: fW[k*64 + lr] = W[wrow(R0+lr)][k]
    {
        int lr   = tid & 63;
        int kb   = (tid >> 6) * 64;
        int grow = R0 + lr;
        int wrow = ((grow & 3) << 9) + (grow >> 2);
        const float* src = W + wrow * 256 + kb;
        #pragma unroll 8
        for (int k = 0; k < 64; k++)
            fW[(kb + k) * 64 + lr] = src[k];
    }

    float bv[8];
    #pragma unroll
    for (int r = 0; r < 8; r++) {
        int grow = R0 + w * 8 + r;
        bv[r] = bias[((grow & 3) << 9) + (grow >> 2)];
    }
    __syncthreads();

    for (int tl = 0; tl < 32; tl++) {
        int t = t0 + tl;
        __syncthreads();
        #pragma unroll
        for (int bi = 0; bi < 4; bi++) {
            int b = w + bi * 8;
            #pragma unroll
            for (int kh = 0; kh < 2; kh++) {
                int k4 = kh * 32 + lane;
                float4 v = *(const float4*)(x + ((size_t)(b * 512 + t)) * 256 + k4 * 4);
                sX[k4 * 33 + b] = v;
            }
        }
        __syncthreads();

        unsigned long long acc0 = 0, acc1 = 0, acc2 = 0, acc3 = 0;
        const unsigned long long* wbase = sW + w * 4;
        #pragma unroll 4
        for (int k4 = 0; k4 < 64; k4++) {
            float4 xv = sX[k4 * 33 + lane];
            #pragma unroll
            for (int kk = 0; kk < 4; kk++) {
                float xs = (&xv.x)[kk];
                unsigned long long hh = pk2(xs, xs);
                const unsigned long long* wp = wbase + (k4 * 4 + kk) * 32;
                ulonglong2 wa = *(const ulonglong2*)(wp);
                ulonglong2 wc = *(const ulonglong2*)(wp + 2);
                fma2(acc0, hh, wa.x);
                fma2(acc1, hh, wa.y);
                fma2(acc2, hh, wc.x);
                fma2(acc3, hh, wc.y);
            }
        }

        // ---- store 8 rows for this lane's batch: [d][t][b=lane][R0+w*8 .. +8]
        float* outp = g_xp + ((size_t)((d * 512 + t) * 32) + lane) * 2048 + R0 + w * 8;
        float f0, f1, f2, f3;
        float4 v0, v1;
        upk2(acc0, f0, f1); upk2(acc1, f2, f3);
        v0.x = f0 + bv[0]; v0.y = f1 + bv[1]; v0.z = f2 + bv[2]; v0.w = f3 + bv[3];
        upk2(acc2, f0, f1); upk2(acc3, f2, f3);
        v1.x = f0 + bv[4]; v1.y = f1 + bv[5]; v1.z = f2 + bv[6]; v1.w = f3 + bv[7];
        *(float4*)(outp)     = v0;
        *(float4*)(outp + 4) = v1;
    }
}

// ==================================================================================
// Phase B: persistent recurrent kernel (v8: HMMA mma.sync, 3-pass split precision).
// 128 CTAs x 256 thr, ~134KB smem, 1 CTA/SM, co-resident => flag-spin safe.
// CTA bid: d = bid>>6, p = bid&63 owns units j0 = p*8 (=32 gate rows, M=32).
// Per step: D[32,32] = W[32,512] x h[32,512]^T, computed as
//   Whi*hhi + Whi*hlo + Wlo*hhi  (fp16 operands, f32 accumulate; err ~1e-5)
// via mma.sync.m16n8k16: 8 warps = (mi 0..1) x (ni 0..3), 32 k-chunks each.
// SMEM rows padded to 1040B so each ldmatrix (8 rows x 16B) hits all 32 banks once.
// Epilogue: warps dump D to smem, 256-thr finalize (thread = (ju=tid&7, b=tid>>3)),
// c in f32 reg, publish h hi/lo fp16 (16B-contiguous per b-row) + f32 out, flag rel.
// ==================================================================================
#define ROWB   1040                      // padded row stride (bytes) for ldmatrix
#define A_HI   0
#define A_LO   (A_HI + 32 * ROWB)        // 33280
#define B_HI   (A_LO + 32 * ROWB)        // 66560
#define B_LO   (B_HI + 32 * ROWB)        // 99840
#define DST_O  (B_LO + 32 * ROWB)        // 133120 ; float[32*33] = 4224B
#define RECUR_SMEM (DST_O + 4224)

__global__ __launch_bounds__(256, 1) void k_recur(
    const float* __restrict__ Whf,
    const float* __restrict__ Whb,
    float* __restrict__ out)
{
    extern __shared__ char smem[];
    const uint32_t sb = smem_to_u32(smem);
    float* Dst = (float*)(smem + DST_O);

    const int bid  = blockIdx.x;
    const int d    = bid >> 6;
    const int p    = bid & 63;
    const int j0   = p * 8;
    const int tid  = threadIdx.x;
    const int lane = tid & 31;
    const int wid  = tid >> 5;
    const int mi   = wid >> 2;           // 0..1  m-tile (rows mi*16..+16)
    const int ni   = wid & 3;            // 0..3  n-tile (batches ni*8..+8)
    const float* Wh = d ? Whb : Whf;

    // ---- A fill: W rows (ju*4+g) -> fp16 hi/lo, padded rows
    for (int idx = tid; idx < 2 * 32 * 512; idx += 256) {
        int op  = idx >> 14;
        int rem = idx & 16383;
        int row = rem >> 9;
        int k   = rem & 511;
        int ju  = row >> 2, g = row & 3;
        float wv = Wh[((size_t)(g * 512 + j0 + ju)) * 512 + k];
        __half hi = __float2half_rn(wv);
        __half val = op ? __float2half_rn(wv - __half2float(hi)) : hi;
        *(__half*)(smem + (op ? A_LO : A_HI) + row * ROWB + k * 2) = val;
    }
    __syncthreads();

    unsigned* flags  = g_flags + d * 64 * 32;
    unsigned* myflag = g_flags + (size_t)bid * 32;
    __half*   hsd    = g_hs + (size_t)d * 2 * 2 * 32 * 512;   // [parity][op][b][k]

    // ldmatrix per-lane offsets (within a pass region), chunk kc adds kc*32 bytes
    const uint32_t a_off = (uint32_t)(mi * 16 + (lane & 15)) * ROWB + ((lane >> 4) & 1) * 16;
    const int      l15   = lane & 15;
    const uint32_t b_off = (uint32_t)(ni * 8 + (l15 & 7)) * ROWB + (l15 >> 3) * 16;

    // finalize identities: thread -> (ju = tid&7, b = tid>>3)
    const int ju_f = tid & 7;
    const int b_f  = tid >> 3;
    const int jg_f = j0 + ju_f;
    float c_st = 0.0f;

    // xp prefetch for step 0: one float4 = 4 gates of (jg_f, b_f)
    float4 xg;
    {
        const int tt0 = d ? 511 : 0;
        xg = *(const float4*)(g_xp + ((size_t)((d * 512 + tt0) * 32) + b_f) * 2048 + jg_f * 4);
    }

    for (int s = 0; s < 512; s++) {
        const int tt = d ? (511 - s) : s;

        // ---- (0) wait for all 64 producers of this direction
        if (tid < 64) {
            while (ld_acquire_gpu(flags + tid * 32) < (unsigned)s) { }
        }
        __syncthreads();

        // ---- (1) stage h hi/lo (64KB) global -> padded smem, 16B copies
        {
            const uint4* hp = (const uint4*)(hsd + (size_t)(s & 1) * 2 * 32 * 512);
            #pragma unroll
            for (int i = 0; i < 16; i++) {
                int id  = tid + i * 256;      // 0..4095
                int op  = id >> 11;
                int b   = (id >> 6) & 31;
                int k16 = id & 63;
                uint4 v = hp[id];
                *(uint4*)(smem + (op ? B_LO : B_HI) + b * ROWB + k16 * 16) = v;
            }
        }
        __syncthreads();

        // ---- (2) HMMA: 32 k-chunks x 3 passes, 3 independent accumulator chains
        float accA[4] = {0.f, 0.f, 0.f, 0.f};   // Whi * hhi
        float accB[4] = {0.f, 0.f, 0.f, 0.f};   // Whi * hlo
        float accC[4] = {0.f, 0.f, 0.f, 0.f};   // Wlo * hhi
        {
            uint32_t aH = sb + A_HI + a_off;
            uint32_t aL = sb + A_LO + a_off;
            uint32_t bH = sb + B_HI + b_off;
            uint32_t bL = sb + B_LO + b_off;
            #pragma unroll 4
            for (int kc = 0; kc < 32; kc++) {
                uint32_t ahi[4], alo[4], bhi[2], blo[2];
                ldm_x4(ahi[0], ahi[1], ahi[2], ahi[3], aH + kc * 32);
                ldm_x2(bhi[0], bhi[1], bH + kc * 32);
                ldm_x4(alo[0], alo[1], alo[2], alo[3], aL + kc * 32);
                ldm_x2(blo[0], blo[1], bL + kc * 32);
                mma16816(accA, ahi, bhi);
                mma16816(accB, ahi, blo);
                mma16816(accC, alo, bhi);
            }
        }

        // ---- (3) dump D tile to smem: row = mi*16 + lane/4 (+8), col = ni*8 + (lane%4)*2
        {
            int rw = mi * 16 + (lane >> 2);
            int cw = ni * 8 + (lane & 3) * 2;
            Dst[rw * 33 + cw]           = accA[0] + accB[0] + accC[0];
            Dst[rw * 33 + cw + 1]       = accA[1] + accB[1] + accC[1];
            Dst[(rw + 8) * 33 + cw]     = accA[2] + accB[2] + accC[2];
            Dst[(rw + 8) * 33 + cw + 1] = accA[3] + accB[3] + accC[3];
        }
        __syncthreads();

        // ---- (4) finalize: thread owns (unit jg_f, batch b_f)
        {
            const float* db = Dst + (4 * ju_f) * 33 + b_f;
            float gi = sigmoid_t(db[0]      + xg.x);
            float gf = sigmoid_t(db[33]     + xg.y);
            float gg = tanh_fast(db[66]     + xg.z);
            float go = sigmoid_t(db[99]     + xg.w);
            c_st = gf * c_st + gi * gg;
            float h = go * tanh_fast(c_st);

            __half hi = __float2half_rn(h);
            __half lo = __float2half_rn(h - __half2float(hi));
            __half* hw = hsd + (size_t)((s + 1) & 1) * 2 * 32 * 512;
            hw[b_f * 512 + jg_f]              = hi;   // 8 units -> 16B contiguous per b-row
            hw[16384 + b_f * 512 + jg_f]      = lo;
            out[((size_t)b_f * 512 + tt) * 1024 + d * 512 + jg_f] = h;

            // prefetch xp for step s+1
            if (s + 1 < 512) {
                const int ttn = d ? (510 - s) : (s + 1);
                xg = *(const float4*)(g_xp + ((size_t)((d * 512 + ttn) * 32) + b_f) * 2048 + jg_f * 4);
            }
        }

        // ---- (5) publish
        __syncthreads();
        if (tid == 0) st_release_gpu(myflag, (unsigned)(s + 1));
    }
}

// ==================================================================================
extern "C" void kernel_launch(void* const* d_in, const int* in_sizes, int n_in,
                              void* d_out, int out_size)
{
    const float* x    = (const float*)d_in[0];
    const float* Wihf = (const float*)d_in[1];
    const float* Whhf = (const float*)d_in[2];
    const float* bf   = (const float*)d_in[3];
    const float* Wihb = (const float*)d_in[4];
    const float* Whhb = (const float*)d_in[5];
    const float* bb   = (const float*)d_in[6];
    float* out = (float*)d_out;

    cudaFuncSetAttribute(k_xproj, cudaFuncAttributeMaxDynamicSharedMemorySize, XPROJ_SMEM);
    cudaFuncSetAttribute(k_recur, cudaFuncAttributeMaxDynamicSharedMemorySize, RECUR_SMEM);

    k_xproj<<<dim3(16, 32, 2), 256, XPROJ_SMEM>>>(x, Wihf, bf, Wihb, bb);
    k_recur<<<128, 256, RECUR_SMEM>>>(Whhf, Whhb, out);
}

// round 11
// speedup vs baseline: 1.7367x; 1.2118x over previous
#include <cuda_runtime.h>
#include <cuda_fp16.h>
#include <cstdint>
#include <cstddef>

// Problem constants
#define NB 32
#define NT 512
#define NI 256
#define NH 512

// -------------------- device scratch (no allocations allowed) --------------------
// xp layout: [d][t][b(32)][row(2048)], row = unit*4 + gate  (gate: 0=i,1=f,2=g,3=o)
__device__ float    g_xp[2u * 512u * 32u * 2048u];   // 268 MB
// h split-fp16 double buffer: [d][parity][op(hi/lo)][b(32)][k(512)] __half
__device__ __half   g_hs[2 * 2 * 2 * 32 * 512];
// per-producer step flags: flag[d][p] at stride 32 u32. 64 producers per dir.
__device__ unsigned g_flags[2 * 64 * 32];

// -------------------- helpers --------------------
__device__ __forceinline__ float tanh_fast(float x) {
    float r;
    asm("tanh.approx.f32 %0, %1;" : "=f"(r) : "f"(x));
    return r;
}
__device__ __forceinline__ float sigmoid_t(float x) {   // 0.5 + 0.5*tanh(x/2)
    return 0.5f + 0.5f * tanh_fast(0.5f * x);
}
__device__ __forceinline__ unsigned ld_acquire_gpu(const unsigned* p) {
    unsigned v;
    asm volatile("ld.acquire.gpu.u32 %0, [%1];" : "=r"(v) : "l"(p) : "memory");
    return v;
}
__device__ __forceinline__ void st_release_gpu(unsigned* p, unsigned v) {
    asm volatile("st.release.gpu.u32 [%0], %1;" :: "l"(p), "r"(v) : "memory");
}
__device__ __forceinline__ uint32_t smem_to_u32(const void* smem_ptr) {
    uint32_t addr;
    asm("{ .reg .u64 tmp; cvta.to.shared.u64 tmp, %1; cvt.u32.u64 %0, tmp; }"
        : "=r"(addr) : "l"(smem_ptr));
    return addr;
}

// ldmatrix (sm_75+), mma.sync m16n8k16 f16->f32 (sm_80+), cp.async (sm_80+)
__device__ __forceinline__ void ldm_x4(uint32_t& r0, uint32_t& r1, uint32_t& r2, uint32_t& r3,
                                       uint32_t addr) {
    asm volatile("ldmatrix.sync.aligned.m8n8.x4.shared.b16 {%0,%1,%2,%3}, [%4];"
        : "=r"(r0), "=r"(r1), "=r"(r2), "=r"(r3) : "r"(addr));
}
__device__ __forceinline__ void ldm_x2(uint32_t& r0, uint32_t& r1, uint32_t addr) {
    asm volatile("ldmatrix.sync.aligned.m8n8.x2.shared.b16 {%0,%1}, [%2];"
        : "=r"(r0), "=r"(r1) : "r"(addr));
}
__device__ __forceinline__ void mma16816(float* d, const uint32_t* a, const uint32_t* b) {
    asm volatile(
        "mma.sync.aligned.m16n8k16.row.col.f32.f16.f16.f32 "
        "{%0,%1,%2,%3}, {%4,%5,%6,%7}, {%8,%9}, {%0,%1,%2,%3};"
        : "+f"(d[0]), "+f"(d[1]), "+f"(d[2]), "+f"(d[3])
        : "r"(a[0]), "r"(a[1]), "r"(a[2]), "r"(a[3]), "r"(b[0]), "r"(b[1]));
}
#define CP_ASYNC16(smem_u32, gptr) \
    asm volatile("cp.async.cg.shared.global [%0], [%1], 16;" :: "r"(smem_u32), "l"(gptr))
#define CP_COMMIT()  asm volatile("cp.async.commit_group;" ::: "memory")
#define CP_WAIT0()   asm volatile("cp.async.wait_group 0;" ::: "memory")

// split a float into fp16 hi + fp16 lo
__device__ __forceinline__ void split16(float v, __half& hi, __half& lo) {
    hi = __float2half_rn(v);
    lo = __float2half_rn(v - __half2float(hi));
}

// ==================================================================================
// Phase A (v2): HMMA input projections.
// xp[d][t][b][row] = sum_i x[b][t][i] * W_ih[d][wrow(row)][i] + bias, row = ju*4+g,
// wrow = (row&3)*512 + (row>>2).
// CTA = (row-block 128, t-block 32, dir). A = W rows hi/lo staged once (135KB);
// per t: stage x[t] [32,256] hi/lo, 3-pass mma.sync (M=128, N=32, K=256).
// Warp = m-tile (16 rows); full N=32 per warp (4 n-tiles).
// Init of g_hs/g_flags fused into first 8 CTAs.
// ==================================================================================
#define XROWB  528                          // padded fp16 row stride (bytes)
#define XA_HI  0
#define XA_LO  (XA_HI + 128 * XROWB)        // 67584
#define XB_HI  (XA_LO + 128 * XROWB)        // 135168
#define XB_LO  (XB_HI + 32 * XROWB)         // 152064
#define XDST   (XB_LO + 32 * XROWB)         // 168960 ; float[128*33] = 16896
#define XBIAS  (XDST + 16896)               // 185856 ; float[128]
#define XPROJ_SMEM (XBIAS + 640)

__global__ __launch_bounds__(256, 1) void k_xproj(
    const float* __restrict__ x,
    const float* __restrict__ Wf, const float* __restrict__ bf,
    const float* __restrict__ Wb, const float* __restrict__ bb)
{
    extern __shared__ char smem[];
    const uint32_t sb = smem_to_u32(smem);
    float* Dst   = (float*)(smem + XDST);
    float* biasS = (float*)(smem + XBIAS);

    const int d    = blockIdx.z;
    const int R0   = blockIdx.x * 128;
    const int t0   = blockIdx.y * 32;
    const int tid  = threadIdx.x;
    const int lane = tid & 31;
    const int wid  = tid >> 5;
    const float* W    = d ? Wb : Wf;
    const float* bias = d ? bb : bf;

    // ---- fused init: zero g_hs parity 0 (both dirs, hi+lo) + flags
    if (blockIdx.z == 0 && blockIdx.y == 0 && blockIdx.x < 8) {
        int t = blockIdx.x * 256 + tid;   // 0..2047
        #pragma unroll
        for (int r = 0; r < 4; r++) {
            int dd = r >> 1, op = r & 1;
            uint4* z = (uint4*)&g_hs[(((size_t)dd * 2 + 0) * 2 + op) * 32 * 512];
            z[t] = make_uint4(0, 0, 0, 0);
        }
        #pragma unroll
        for (int i = 0; i < 2; i++)
            g_flags[t + i * 2048] = 0u;
    }

    // ---- A stage: W rows (R0..R0+128) -> fp16 hi/lo, padded rows
    for (int idx = tid; idx < 8192; idx += 256) {   // float4 units over [128][64]
        int r  = idx >> 6;
        int i4 = idx & 63;
        int grow = R0 + r;
        int wrow = ((grow & 3) << 9) + (grow >> 2);
        float4 v = *(const float4*)(W + (size_t)wrow * 256 + i4 * 4);
        __half h0, l0, h1, l1, h2, l2, h3, l3;
        split16(v.x, h0, l0); split16(v.y, h1, l1);
        split16(v.z, h2, l2); split16(v.w, h3, l3);
        uint2 hv, lv;
        hv.x = __halves2half2(h0, h1).x ? 0 : 0;  // placeholder avoided below
        // pack via memcpy-safe unions
        __half2 hh01 = __halves2half2(h0, h1), hh23 = __halves2half2(h2, h3);
        __half2 ll01 = __halves2half2(l0, l1), ll23 = __halves2half2(l2, l3);
        hv.x = *(uint32_t*)&hh01; hv.y = *(uint32_t*)&hh23;
        lv.x = *(uint32_t*)&ll01; lv.y = *(uint32_t*)&ll23;
        *(uint2*)(smem + XA_HI + r * XROWB + i4 * 8) = hv;
        *(uint2*)(smem + XA_LO + r * XROWB + i4 * 8) = lv;
    }
    if (tid < 128) {
        int grow = R0 + tid;
        biasS[tid] = bias[((grow & 3) << 9) + (grow >> 2)];
    }
    __syncthreads();

    // ldmatrix lane offsets (identical formulas to the proven recur kernel)
    const int mi = wid;   // 8 warps = 8 m-tiles of 16 rows
    const uint32_t a_off = (uint32_t)(mi * 16 + (lane & 15)) * XROWB + ((lane >> 4) & 1) * 16;
    const int b_row = (lane & 7) + ((lane & 16) >> 1);          // n8 pair mapping for x4
    const uint32_t b_off = (uint32_t)b_row * XROWB + ((lane >> 3) & 1) * 16;

    const int b_w  = tid >> 3;   // out-write: batch
    const int rq_w = tid & 7;    // out-write: 16-row group

    for (int tl = 0; tl < 32; tl++) {
        const int t = t0 + tl;
        __syncthreads();   // previous Dst consumed, B free

        // ---- stage x[t]: [32,256] f32 -> hi/lo fp16
        #pragma unroll
        for (int j = 0; j < 8; j++) {
            int l  = tid + j * 256;        // float4 units over [32][64]
            int b  = l >> 6;
            int i4 = l & 63;
            float4 v = *(const float4*)(x + ((size_t)(b * 512 + t)) * 256 + i4 * 4);
            __half h0, l0, h1, l1, h2, l2, h3, l3;
            split16(v.x, h0, l0); split16(v.y, h1, l1);
            split16(v.z, h2, l2); split16(v.w, h3, l3);
            __half2 hh01 = __halves2half2(h0, h1), hh23 = __halves2half2(h2, h3);
            __half2 ll01 = __halves2half2(l0, l1), ll23 = __halves2half2(l2, l3);
            uint2 hv, lv;
            hv.x = *(uint32_t*)&hh01; hv.y = *(uint32_t*)&hh23;
            lv.x = *(uint32_t*)&ll01; lv.y = *(uint32_t*)&ll23;
            *(uint2*)(smem + XB_HI + b * XROWB + i4 * 8) = hv;
            *(uint2*)(smem + XB_LO + b * XROWB + i4 * 8) = lv;
        }
        __syncthreads();

        // ---- 3-pass MMA over K=256 (16 chunks)
        float accA[4][4], accB[4][4], accC[4][4];
        #pragma unroll
        for (int nt = 0; nt < 4; nt++)
            #pragma unroll
            for (int e = 0; e < 4; e++) { accA[nt][e] = 0.f; accB[nt][e] = 0.f; accC[nt][e] = 0.f; }

        {
            uint32_t aH = sb + XA_HI + a_off;
            uint32_t aL = sb + XA_LO + a_off;
            uint32_t bH0 = sb + XB_HI + b_off;
            uint32_t bH1 = bH0 + 16 * XROWB;
            uint32_t bL0 = sb + XB_LO + b_off;
            uint32_t bL1 = bL0 + 16 * XROWB;
            #pragma unroll 2
            for (int kc = 0; kc < 16; kc++) {
                uint32_t ahi[4], alo[4], bh[8], bl[8];
                ldm_x4(ahi[0], ahi[1], ahi[2], ahi[3], aH + kc * 32);
                ldm_x4(alo[0], alo[1], alo[2], alo[3], aL + kc * 32);
                ldm_x4(bh[0], bh[1], bh[2], bh[3], bH0 + kc * 32);   // n0-15
                ldm_x4(bh[4], bh[5], bh[6], bh[7], bH1 + kc * 32);   // n16-31
                ldm_x4(bl[0], bl[1], bl[2], bl[3], bL0 + kc * 32);
                ldm_x4(bl[4], bl[5], bl[6], bl[7], bL1 + kc * 32);
                #pragma unroll
                for (int nt = 0; nt < 4; nt++) {
                    mma16816(accA[nt], ahi, bh + nt * 2);
                    mma16816(accB[nt], ahi, bl + nt * 2);
                    mma16816(accC[nt], alo, bh + nt * 2);
                }
            }
        }

        // ---- dump D tile to Dst
        {
            int rw  = mi * 16 + (lane >> 2);
            int cw0 = (lane & 3) * 2;
            #pragma unroll
            for (int nt = 0; nt < 4; nt++) {
                int col = nt * 8 + cw0;
                Dst[rw * 33 + col]           = accA[nt][0] + accB[nt][0] + accC[nt][0];
                Dst[rw * 33 + col + 1]       = accA[nt][1] + accB[nt][1] + accC[nt][1];
                Dst[(rw + 8) * 33 + col]     = accA[nt][2] + accB[nt][2] + accC[nt][2];
                Dst[(rw + 8) * 33 + col + 1] = accA[nt][3] + accB[nt][3] + accC[nt][3];
            }
        }
        __syncthreads();

        // ---- write out with bias: thread = (b, 16-row group), coalesced float4
        {
            float* op = g_xp + ((size_t)((d * 512 + t) * 32) + b_w) * 2048 + R0 + rq_w * 16;
            #pragma unroll
            for (int e = 0; e < 16; e += 4) {
                int r = rq_w * 16 + e;
                float4 o;
                o.x = Dst[(r + 0) * 33 + b_w] + biasS[r + 0];
                o.y = Dst[(r + 1) * 33 + b_w] + biasS[r + 1];
                o.z = Dst[(r + 2) * 33 + b_w] + biasS[r + 2];
                o.w = Dst[(r + 3) * 33 + b_w] + biasS[r + 3];
                *(float4*)(op + e) = o;
            }
        }
    }
}

// ==================================================================================
// Phase B: persistent recurrent kernel (v8.1: HMMA + cp.async h stage).
// Identical to the passing v8 except the h staging uses cp.async (LDGSTS).
// ==================================================================================
#define ROWB   1040
#define A_HI   0
#define A_LO   (A_HI + 32 * ROWB)
#define B_HI   (A_LO + 32 * ROWB)
#define B_LO   (B_HI + 32 * ROWB)
#define DST_O  (B_LO + 32 * ROWB)
#define RECUR_SMEM (DST_O + 4224)

__global__ __launch_bounds__(256, 1) void k_recur(
    const float* __restrict__ Whf,
    const float* __restrict__ Whb,
    float* __restrict__ out)
{
    extern __shared__ char smem[];
    const uint32_t sb = smem_to_u32(smem);
    float* Dst = (float*)(smem + DST_O);

    const int bid  = blockIdx.x;
    const int d    = bid >> 6;
    const int p    = bid & 63;
    const int j0   = p * 8;
    const int tid  = threadIdx.x;
    const int lane = tid & 31;
    const int wid  = tid >> 5;
    const int mi   = wid >> 2;
    const int ni   = wid & 3;
    const float* Wh = d ? Whb : Whf;

    // ---- A fill: W rows (ju*4+g) -> fp16 hi/lo, padded rows
    for (int idx = tid; idx < 2 * 32 * 512; idx += 256) {
        int op  = idx >> 14;
        int rem = idx & 16383;
        int row = rem >> 9;
        int k   = rem & 511;
        int ju  = row >> 2, g = row & 3;
        float wv = Wh[((size_t)(g * 512 + j0 + ju)) * 512 + k];
        __half hi = __float2half_rn(wv);
        __half val = op ? __float2half_rn(wv - __half2float(hi)) : hi;
        *(__half*)(smem + (op ? A_LO : A_HI) + row * ROWB + k * 2) = val;
    }
    __syncthreads();

    unsigned* flags  = g_flags + d * 64 * 32;
    unsigned* myflag = g_flags + (size_t)bid * 32;
    __half*   hsd    = g_hs + (size_t)d * 2 * 2 * 32 * 512;   // [parity][op][b][k]

    const uint32_t a_off = (uint32_t)(mi * 16 + (lane & 15)) * ROWB + ((lane >> 4) & 1) * 16;
    const int      l15   = lane & 15;
    const uint32_t b_off = (uint32_t)(ni * 8 + (l15 & 7)) * ROWB + (l15 >> 3) * 16;

    const int ju_f = tid & 7;
    const int b_f  = tid >> 3;
    const int jg_f = j0 + ju_f;
    float c_st = 0.0f;

    float4 xg;
    {
        const int tt0 = d ? 511 : 0;
        xg = *(const float4*)(g_xp + ((size_t)((d * 512 + tt0) * 32) + b_f) * 2048 + jg_f * 4);
    }

    for (int s = 0; s < 512; s++) {
        const int tt = d ? (511 - s) : s;

        // ---- (0) wait for all 64 producers of this direction
        if (tid < 64) {
            while (ld_acquire_gpu(flags + tid * 32) < (unsigned)s) { }
        }
        __syncthreads();

        // ---- (1) stage h hi/lo (64KB) global -> padded smem via cp.async
        {
            const uint4* hp = (const uint4*)(hsd + (size_t)(s & 1) * 2 * 32 * 512);
            #pragma unroll
            for (int i = 0; i < 16; i++) {
                int id  = tid + i * 256;
                int op  = id >> 11;
                int b   = (id >> 6) & 31;
                int k16 = id & 63;
                uint32_t daddr = sb + (op ? B_LO : B_HI) + b * ROWB + k16 * 16;
                CP_ASYNC16(daddr, hp + id);
            }
            CP_COMMIT();
            CP_WAIT0();
        }
        __syncthreads();

        // ---- (2) HMMA: 32 k-chunks x 3 passes
        float accA[4] = {0.f, 0.f, 0.f, 0.f};
        float accB[4] = {0.f, 0.f, 0.f, 0.f};
        float accC[4] = {0.f, 0.f, 0.f, 0.f};
        {
            uint32_t aH = sb + A_HI + a_off;
            uint32_t aL = sb + A_LO + a_off;
            uint32_t bH = sb + B_HI + b_off;
            uint32_t bL = sb + B_LO + b_off;
            #pragma unroll 4
            for (int kc = 0; kc < 32; kc++) {
                uint32_t ahi[4], alo[4], bhi[2], blo[2];
                ldm_x4(ahi[0], ahi[1], ahi[2], ahi[3], aH + kc * 32);
                ldm_x2(bhi[0], bhi[1], bH + kc * 32);
                ldm_x4(alo[0], alo[1], alo[2], alo[3], aL + kc * 32);
                ldm_x2(blo[0], blo[1], bL + kc * 32);
                mma16816(accA, ahi, bhi);
                mma16816(accB, ahi, blo);
                mma16816(accC, alo, bhi);
            }
        }

        // ---- (3) dump D tile
        {
            int rw = mi * 16 + (lane >> 2);
            int cw = ni * 8 + (lane & 3) * 2;
            Dst[rw * 33 + cw]           = accA[0] + accB[0] + accC[0];
            Dst[rw * 33 + cw + 1]       = accA[1] + accB[1] + accC[1];
            Dst[(rw + 8) * 33 + cw]     = accA[2] + accB[2] + accC[2];
            Dst[(rw + 8) * 33 + cw + 1] = accA[3] + accB[3] + accC[3];
        }
        __syncthreads();

        // ---- (4) finalize: thread owns (unit jg_f, batch b_f)
        {
            const float* db = Dst + (4 * ju_f) * 33 + b_f;
            float gi = sigmoid_t(db[0]  + xg.x);
            float gf = sigmoid_t(db[33] + xg.y);
            float gg = tanh_fast(db[66] + xg.z);
            float go = sigmoid_t(db[99] + xg.w);
            c_st = gf * c_st + gi * gg;
            float h = go * tanh_fast(c_st);

            __half hi = __float2half_rn(h);
            __half lo = __float2half_rn(h - __half2float(hi));
            __half* hw = hsd + (size_t)((s + 1) & 1) * 2 * 32 * 512;
            hw[b_f * 512 + jg_f]         = hi;
            hw[16384 + b_f * 512 + jg_f] = lo;
            out[((size_t)b_f * 512 + tt) * 1024 + d * 512 + jg_f] = h;

            if (s + 1 < 512) {
                const int ttn = d ? (510 - s) : (s + 1);
                xg = *(const float4*)(g_xp + ((size_t)((d * 512 + ttn) * 32) + b_f) * 2048 + jg_f * 4);
            }
        }

        // ---- (5) publish
        __syncthreads();
        if (tid == 0) st_release_gpu(myflag, (unsigned)(s + 1));
    }
}

// ==================================================================================
extern "C" void kernel_launch(void* const* d_in, const int* in_sizes, int n_in,
                              void* d_out, int out_size)
{
    const float* x    = (const float*)d_in[0];
    const float* Wihf = (const float*)d_in[1];
    const float* Whhf = (const float*)d_in[2];
    const float* bf   = (const float*)d_in[3];
    const float* Wihb = (const float*)d_in[4];
    const float* Whhb = (const float*)d_in[5];
    const float* bb   = (const float*)d_in[6];
    float* out = (float*)d_out;

    cudaFuncSetAttribute(k_xproj, cudaFuncAttributeMaxDynamicSharedMemorySize, XPROJ_SMEM);
    cudaFuncSetAttribute(k_recur, cudaFuncAttributeMaxDynamicSharedMemorySize, RECUR_SMEM);

    k_xproj<<<dim3(16, 16, 2), 256, XPROJ_SMEM>>>(x, Wihf, bf, Wihb, bb);
    k_recur<<<128, 256, RECUR_SMEM>>>(Whhf, Whhb, out);
}

// round 12
// speedup vs baseline: 1.7634x; 1.0154x over previous
#include <cuda_runtime.h>
#include <cuda_fp16.h>
#include <cstdint>
#include <cstddef>

// Problem constants
#define NB 32
#define NT 512
#define NI 256
#define NH 512

// -------------------- device scratch (no allocations allowed) --------------------
// xp layout: [d][t][b(32)][row(2048)], row = unit*4 + gate  (gate: 0=i,1=f,2=g,3=o)
__device__ float    g_xp[2u * 512u * 32u * 2048u];   // 268 MB
// h split-fp16 double buffer: [d][parity][op(hi/lo)][b(32)][k(512)] __half
__device__ __half   g_hs[2 * 2 * 2 * 32 * 512];
// per-producer step flags: flag[d][p] at stride 32 u32. 64 producers per dir.
__device__ unsigned g_flags[2 * 64 * 32];

// -------------------- helpers --------------------
__device__ __forceinline__ float tanh_fast(float x) {
    float r;
    asm("tanh.approx.f32 %0, %1;" : "=f"(r) : "f"(x));
    return r;
}
__device__ __forceinline__ float sigmoid_t(float x) {   // 0.5 + 0.5*tanh(x/2)
    return 0.5f + 0.5f * tanh_fast(0.5f * x);
}
__device__ __forceinline__ unsigned ld_acquire_gpu(const unsigned* p) {
    unsigned v;
    asm volatile("ld.acquire.gpu.u32 %0, [%1];" : "=r"(v) : "l"(p) : "memory");
    return v;
}
__device__ __forceinline__ void st_release_gpu(unsigned* p, unsigned v) {
    asm volatile("st.release.gpu.u32 [%0], %1;" :: "l"(p), "r"(v) : "memory");
}
__device__ __forceinline__ uint32_t smem_to_u32(const void* smem_ptr) {
    uint32_t addr;
    asm("{ .reg .u64 tmp; cvta.to.shared.u64 tmp, %1; cvt.u32.u64 %0, tmp; }"
        : "=r"(addr) : "l"(smem_ptr));
    return addr;
}

// ldmatrix (sm_75+), mma.sync m16n8k16 f16->f32 (sm_80+), cp.async (sm_80+)
__device__ __forceinline__ void ldm_x4(uint32_t& r0, uint32_t& r1, uint32_t& r2, uint32_t& r3,
                                       uint32_t addr) {
    asm volatile("ldmatrix.sync.aligned.m8n8.x4.shared.b16 {%0,%1,%2,%3}, [%4];"
        : "=r"(r0), "=r"(r1), "=r"(r2), "=r"(r3) : "r"(addr));
}
__device__ __forceinline__ void mma16816(float* d, const uint32_t* a, const uint32_t* b) {
    asm volatile(
        "mma.sync.aligned.m16n8k16.row.col.f32.f16.f16.f32 "
        "{%0,%1,%2,%3}, {%4,%5,%6,%7}, {%8,%9}, {%0,%1,%2,%3};"
        : "+f"(d[0]), "+f"(d[1]), "+f"(d[2]), "+f"(d[3])
        : "r"(a[0]), "r"(a[1]), "r"(a[2]), "r"(a[3]), "r"(b[0]), "r"(b[1]));
}
#define CP_ASYNC16(smem_u32, gptr) \
    asm volatile("cp.async.cg.shared.global [%0], [%1], 16;" :: "r"(smem_u32), "l"(gptr))
#define CP_COMMIT()  asm volatile("cp.async.commit_group;" ::: "memory")
#define CP_WAIT0()   asm volatile("cp.async.wait_group 0;" ::: "memory")

// split a float into fp16 hi + fp16 lo
__device__ __forceinline__ void split16(float v, __half& hi, __half& lo) {
    hi = __float2half_rn(v);
    lo = __float2half_rn(v - __half2float(hi));
}

// ==================================================================================
// Phase A: HMMA input projections (3-pass split precision, proven in R11).
// xp[d][t][b][row] = sum_i x[b][t][i] * W_ih[d][wrow(row)][i] + bias, row = ju*4+g.
// CTA = (row-block 128, t-block 32, dir). Init of g_hs/g_flags fused into first 8.
// ==================================================================================
#define XROWB  528
#define XA_HI  0
#define XA_LO  (XA_HI + 128 * XROWB)
#define XB_HI  (XA_LO + 128 * XROWB)
#define XB_LO  (XB_HI + 32 * XROWB)
#define XDST   (XB_LO + 32 * XROWB)
#define XBIAS  (XDST + 16896)
#define XPROJ_SMEM (XBIAS + 640)

__global__ __launch_bounds__(256, 1) void k_xproj(
    const float* __restrict__ x,
    const float* __restrict__ Wf, const float* __restrict__ bf,
    const float* __restrict__ Wb, const float* __restrict__ bb)
{
    extern __shared__ char smem[];
    const uint32_t sb = smem_to_u32(smem);
    float* Dst   = (float*)(smem + XDST);
    float* biasS = (float*)(smem + XBIAS);

    const int d    = blockIdx.z;
    const int R0   = blockIdx.x * 128;
    const int t0   = blockIdx.y * 32;
    const int tid  = threadIdx.x;
    const int lane = tid & 31;
    const int wid  = tid >> 5;
    const float* W    = d ? Wb : Wf;
    const float* bias = d ? bb : bf;

    // ---- fused init: zero g_hs parity 0 (both dirs, hi+lo) + flags
    if (blockIdx.z == 0 && blockIdx.y == 0 && blockIdx.x < 8) {
        int t = blockIdx.x * 256 + tid;
        #pragma unroll
        for (int r = 0; r < 4; r++) {
            int dd = r >> 1, op = r & 1;
            uint4* z = (uint4*)&g_hs[(((size_t)dd * 2 + 0) * 2 + op) * 32 * 512];
            z[t] = make_uint4(0, 0, 0, 0);
        }
        #pragma unroll
        for (int i = 0; i < 2; i++)
            g_flags[t + i * 2048] = 0u;
    }

    // ---- A stage: W rows hi/lo
    for (int idx = tid; idx < 8192; idx += 256) {
        int r  = idx >> 6;
        int i4 = idx & 63;
        int grow = R0 + r;
        int wrow = ((grow & 3) << 9) + (grow >> 2);
        float4 v = *(const float4*)(W + (size_t)wrow * 256 + i4 * 4);
        __half h0, l0, h1, l1, h2, l2, h3, l3;
        split16(v.x, h0, l0); split16(v.y, h1, l1);
        split16(v.z, h2, l2); split16(v.w, h3, l3);
        __half2 hh01 = __halves2half2(h0, h1), hh23 = __halves2half2(h2, h3);
        __half2 ll01 = __halves2half2(l0, l1), ll23 = __halves2half2(l2, l3);
        uint2 hv, lv;
        hv.x = *(uint32_t*)&hh01; hv.y = *(uint32_t*)&hh23;
        lv.x = *(uint32_t*)&ll01; lv.y = *(uint32_t*)&ll23;
        *(uint2*)(smem + XA_HI + r * XROWB + i4 * 8) = hv;
        *(uint2*)(smem + XA_LO + r * XROWB + i4 * 8) = lv;
    }
    if (tid < 128) {
        int grow = R0 + tid;
        biasS[tid] = bias[((grow & 3) << 9) + (grow >> 2)];
    }
    __syncthreads();

    const int mi = wid;
    const uint32_t a_off = (uint32_t)(mi * 16 + (lane & 15)) * XROWB + ((lane >> 4) & 1) * 16;
    const int b_row = (lane & 7) + ((lane & 16) >> 1);
    const uint32_t b_off = (uint32_t)b_row * XROWB + ((lane >> 3) & 1) * 16;

    const int b_w  = tid >> 3;
    const int rq_w = tid & 7;

    for (int tl = 0; tl < 32; tl++) {
        const int t = t0 + tl;
        __syncthreads();

        // ---- stage x[t]: [32,256] f32 -> hi/lo fp16
        #pragma unroll
        for (int j = 0; j < 8; j++) {
            int l  = tid + j * 256;
            int b  = l >> 6;
            int i4 = l & 63;
            float4 v = *(const float4*)(x + ((size_t)(b * 512 + t)) * 256 + i4 * 4);
            __half h0, l0, h1, l1, h2, l2, h3, l3;
            split16(v.x, h0, l0); split16(v.y, h1, l1);
            split16(v.z, h2, l2); split16(v.w, h3, l3);
            __half2 hh01 = __halves2half2(h0, h1), hh23 = __halves2half2(h2, h3);
            __half2 ll01 = __halves2half2(l0, l1), ll23 = __halves2half2(l2, l3);
            uint2 hv, lv;
            hv.x = *(uint32_t*)&hh01; hv.y = *(uint32_t*)&hh23;
            lv.x = *(uint32_t*)&ll01; lv.y = *(uint32_t*)&ll23;
            *(uint2*)(smem + XB_HI + b * XROWB + i4 * 8) = hv;
            *(uint2*)(smem + XB_LO + b * XROWB + i4 * 8) = lv;
        }
        __syncthreads();

        // ---- 3-pass MMA over K=256 (16 chunks)
        float accA[4][4], accB[4][4], accC[4][4];
        #pragma unroll
        for (int nt = 0; nt < 4; nt++)
            #pragma unroll
            for (int e = 0; e < 4; e++) { accA[nt][e] = 0.f; accB[nt][e] = 0.f; accC[nt][e] = 0.f; }

        {
            uint32_t aH = sb + XA_HI + a_off;
            uint32_t aL = sb + XA_LO + a_off;
            uint32_t bH0 = sb + XB_HI + b_off;
            uint32_t bH1 = bH0 + 16 * XROWB;
            uint32_t bL0 = sb + XB_LO + b_off;
            uint32_t bL1 = bL0 + 16 * XROWB;
            #pragma unroll 2
            for (int kc = 0; kc < 16; kc++) {
                uint32_t ahi[4], alo[4], bh[8], bl[8];
                ldm_x4(ahi[0], ahi[1], ahi[2], ahi[3], aH + kc * 32);
                ldm_x4(alo[0], alo[1], alo[2], alo[3], aL + kc * 32);
                ldm_x4(bh[0], bh[1], bh[2], bh[3], bH0 + kc * 32);
                ldm_x4(bh[4], bh[5], bh[6], bh[7], bH1 + kc * 32);
                ldm_x4(bl[0], bl[1], bl[2], bl[3], bL0 + kc * 32);
                ldm_x4(bl[4], bl[5], bl[6], bl[7], bL1 + kc * 32);
                #pragma unroll
                for (int nt = 0; nt < 4; nt++) {
                    mma16816(accA[nt], ahi, bh + nt * 2);
                    mma16816(accB[nt], ahi, bl + nt * 2);
                    mma16816(accC[nt], alo, bh + nt * 2);
                }
            }
        }

        // ---- dump D tile to Dst
        {
            int rw  = mi * 16 + (lane >> 2);
            int cw0 = (lane & 3) * 2;
            #pragma unroll
            for (int nt = 0; nt < 4; nt++) {
                int col = nt * 8 + cw0;
                Dst[rw * 33 + col]           = accA[nt][0] + accB[nt][0] + accC[nt][0];
                Dst[rw * 33 + col + 1]       = accA[nt][1] + accB[nt][1] + accC[nt][1];
                Dst[(rw + 8) * 33 + col]     = accA[nt][2] + accB[nt][2] + accC[nt][2];
                Dst[(rw + 8) * 33 + col + 1] = accA[nt][3] + accB[nt][3] + accC[nt][3];
            }
        }
        __syncthreads();

        // ---- write out with bias
        {
            float* op = g_xp + ((size_t)((d * 512 + t) * 32) + b_w) * 2048 + R0 + rq_w * 16;
            #pragma unroll
            for (int e = 0; e < 16; e += 4) {
                int r = rq_w * 16 + e;
                float4 o;
                o.x = Dst[(r + 0) * 33 + b_w] + biasS[r + 0];
                o.y = Dst[(r + 1) * 33 + b_w] + biasS[r + 1];
                o.z = Dst[(r + 2) * 33 + b_w] + biasS[r + 2];
                o.w = Dst[(r + 3) * 33 + b_w] + biasS[r + 3];
                *(float4*)(op + e) = o;
            }
        }
    }
}

// ==================================================================================
// Phase B: persistent recurrent kernel (v9: A-in-registers, 2-pass, x4-B, lane-gated).
// 128 CTAs x 256 thr, ~72KB smem, 1 CTA/SM, co-resident => spin-safe.
// CTA bid: d = bid>>6, p = bid&63 owns units j0 = p*8 (=32 gate rows, M=32).
// D[32,32] = Whi x (hhi + hlo)^T  (W single fp16: err ~1e-4; h exact via hi+lo).
// A fragments (constant!) preloaded to registers once: zero A LDSM in the loop.
// B via ldmatrix x4 covering 2 k-chunks: 32 B-LDSM + 64 mma per warp per step.
// Staging: piece (op,b,k16) depends only on producer k16&63 == tid&63 -> per-lane
// flag poll + immediate cp.async (no block-wide gate before staging).
// ==================================================================================
#define ROWB   1040
#define B_HI   0
#define B_LO   (B_HI + 32 * ROWB)
#define DST_O  (B_LO + 32 * ROWB)            // 66560 ; float[32*33] = 4224
#define AST_O  (DST_O + 4224)                // A staging (reused only at init) 33280
#define RECUR_SMEM (AST_O + 33280)

__global__ __launch_bounds__(256, 1) void k_recur(
    const float* __restrict__ Whf,
    const float* __restrict__ Whb,
    float* __restrict__ out)
{
    extern __shared__ char smem[];
    const uint32_t sb = smem_to_u32(smem);
    float* Dst = (float*)(smem + DST_O);

    const int bid  = blockIdx.x;
    const int d    = bid >> 6;
    const int p    = bid & 63;
    const int j0   = p * 8;
    const int tid  = threadIdx.x;
    const int lane = tid & 31;
    const int wid  = tid >> 5;
    const int mi   = wid >> 2;           // 0..1  m-tile
    const int ni   = wid & 3;            // 0..3  n-tile
    const float* Wh = d ? Whb : Whf;

    // ---- stage W-hi rows (ju*4+g) into AST, then preload A fragments to registers
    for (int idx = tid; idx < 32 * 512; idx += 256) {
        int row = idx >> 9;
        int k   = idx & 511;
        int ju  = row >> 2, g = row & 3;
        float wv = Wh[((size_t)(g * 512 + j0 + ju)) * 512 + k];
        *(__half*)(smem + AST_O + row * ROWB + k * 2) = __float2half_rn(wv);
    }
    __syncthreads();

    uint32_t a_frag[32][4];
    {
        const uint32_t a_off = (uint32_t)(mi * 16 + (lane & 15)) * ROWB + ((lane >> 4) & 1) * 16;
        uint32_t aH = sb + AST_O + a_off;
        #pragma unroll
        for (int kc = 0; kc < 32; kc++)
            ldm_x4(a_frag[kc][0], a_frag[kc][1], a_frag[kc][2], a_frag[kc][3], aH + kc * 32);
    }
    __syncthreads();

    unsigned* flags  = g_flags + d * 64 * 32;
    unsigned* myflag = g_flags + (size_t)bid * 32;
    __half*   hsd    = g_hs + (size_t)d * 2 * 2 * 32 * 512;   // [parity][op][b][k]

    // B x4 lane offset: rows ni*8 + (lane&7); 16B col group (lane>>3)&3 spans 2 chunks
    const uint32_t b_off = (uint32_t)(ni * 8 + (lane & 7)) * ROWB + ((lane >> 3) & 3) * 16;

    const int ju_f = tid & 7;
    const int b_f  = tid >> 3;
    const int jg_f = j0 + ju_f;
    const int myprod = tid & 63;         // the producer this thread's staging depends on
    float c_st = 0.0f;

    float4 xg;
    {
        const int tt0 = d ? 511 : 0;
        xg = *(const float4*)(g_xp + ((size_t)((d * 512 + tt0) * 32) + b_f) * 2048 + jg_f * 4);
    }

    for (int s = 0; s < 512; s++) {
        const int tt = d ? (511 - s) : s;

        // ---- (0+1) per-lane gate + stage: poll ONLY my producer, then cp.async my 16
        // pieces (id = tid + i*256 => k16 = tid&63 = myprod for all i).
        while (ld_acquire_gpu(flags + myprod * 32) < (unsigned)s) { }
        {
            const uint4* hp = (const uint4*)(hsd + (size_t)(s & 1) * 2 * 32 * 512);
            #pragma unroll
            for (int i = 0; i < 16; i++) {
                int id  = tid + i * 256;
                int op  = id >> 11;
                int b   = (id >> 6) & 31;
                int k16 = id & 63;
                uint32_t daddr = sb + (op ? B_LO : B_HI) + b * ROWB + k16 * 16;
                CP_ASYNC16(daddr, hp + id);
            }
            CP_COMMIT();
            CP_WAIT0();
        }
        __syncthreads();

        // ---- (2) HMMA: 16 iter x (2 B-ldsm + 4 mma), A from registers
        float accA[4] = {0.f, 0.f, 0.f, 0.f};   // Whi * hhi
        float accB[4] = {0.f, 0.f, 0.f, 0.f};   // Whi * hlo
        {
            uint32_t bH = sb + B_HI + b_off;
            uint32_t bL = sb + B_LO + b_off;
            #pragma unroll 4
            for (int kc = 0; kc < 32; kc += 2) {
                uint32_t bh[4], bl[4];
                ldm_x4(bh[0], bh[1], bh[2], bh[3], bH + kc * 32);
                ldm_x4(bl[0], bl[1], bl[2], bl[3], bL + kc * 32);
                mma16816(accA, a_frag[kc],     bh);
                mma16816(accA, a_frag[kc + 1], bh + 2);
                mma16816(accB, a_frag[kc],     bl);
                mma16816(accB, a_frag[kc + 1], bl + 2);
            }
        }

        // ---- (3) dump D tile
        {
            int rw = mi * 16 + (lane >> 2);
            int cw = ni * 8 + (lane & 3) * 2;
            Dst[rw * 33 + cw]           = accA[0] + accB[0];
            Dst[rw * 33 + cw + 1]       = accA[1] + accB[1];
            Dst[(rw + 8) * 33 + cw]     = accA[2] + accB[2];
            Dst[(rw + 8) * 33 + cw + 1] = accA[3] + accB[3];
        }
        __syncthreads();

        // ---- (4) finalize: thread owns (unit jg_f, batch b_f)
        {
            const float* db = Dst + (4 * ju_f) * 33 + b_f;
            float gi = sigmoid_t(db[0]  + xg.x);
            float gf = sigmoid_t(db[33] + xg.y);
            float gg = tanh_fast(db[66] + xg.z);
            float go = sigmoid_t(db[99] + xg.w);
            c_st = gf * c_st + gi * gg;
            float h = go * tanh_fast(c_st);

            __half hi = __float2half_rn(h);
            __half lo = __float2half_rn(h - __half2float(hi));
            __half* hw = hsd + (size_t)((s + 1) & 1) * 2 * 32 * 512;
            hw[b_f * 512 + jg_f]         = hi;
            hw[16384 + b_f * 512 + jg_f] = lo;
            out[((size_t)b_f * 512 + tt) * 1024 + d * 512 + jg_f] = h;

            if (s + 1 < 512) {
                const int ttn = d ? (510 - s) : (s + 1);
                xg = *(const float4*)(g_xp + ((size_t)((d * 512 + ttn) * 32) + b_f) * 2048 + jg_f * 4);
            }
        }

        // ---- (5) publish
        __syncthreads();
        if (tid == 0) st_release_gpu(myflag, (unsigned)(s + 1));
    }
}

// ==================================================================================
extern "C" void kernel_launch(void* const* d_in, const int* in_sizes, int n_in,
                              void* d_out, int out_size)
{
    const float* x    = (const float*)d_in[0];
    const float* Wihf = (const float*)d_in[1];
    const float* Whhf = (const float*)d_in[2];
    const float* bf   = (const float*)d_in[3];
    const float* Wihb = (const float*)d_in[4];
    const float* Whhb = (const float*)d_in[5];
    const float* bb   = (const float*)d_in[6];
    float* out = (float*)d_out;

    cudaFuncSetAttribute(k_xproj, cudaFuncAttributeMaxDynamicSharedMemorySize, XPROJ_SMEM);
    cudaFuncSetAttribute(k_recur, cudaFuncAttributeMaxDynamicSharedMemorySize, RECUR_SMEM);

    k_xproj<<<dim3(16, 16, 2), 256, XPROJ_SMEM>>>(x, Wihf, bf, Wihb, bb);
    k_recur<<<128, 256, RECUR_SMEM>>>(Whhf, Whhb, out);
}